// round 7
// baseline (speedup 1.0000x reference)
#include <cuda_runtime.h>

// ROI-Align: img (8,64,64,1024) f32 NHWC, rois (32,4) int32 [x,y,w,h]
// out flat layout: [r][b][py][px][c]  (r-major), 32*8*7*7*1024 floats.
// 4 bins per 512-thread CTA (128 threads/bin, independent, no barriers)
// to cut CTA dispatch ramp; bins ordered b-major for wave L2 locality.
// 8 channels/thread: 32-byte (v4.b64) evict_last loads, one 32-byte
// streaming (.cs v4.b64) output store.

#define POOL 7
#define B 8
#define R 32
#define C 1024
#define W 64
#define BINS_PER_CTA 4

struct F8 { float f[8]; };

__device__ __forceinline__ F8 ldg_el_32B(const void* p) {
    unsigned long long a, b, c, d;
    asm volatile("ld.global.nc.L2::evict_last.v4.b64 {%0,%1,%2,%3}, [%4];"
                 : "=l"(a), "=l"(b), "=l"(c), "=l"(d) : "l"(p));
    F8 r;
    r.f[0] = __uint_as_float((unsigned)(a      )); r.f[1] = __uint_as_float((unsigned)(a >> 32));
    r.f[2] = __uint_as_float((unsigned)(b      )); r.f[3] = __uint_as_float((unsigned)(b >> 32));
    r.f[4] = __uint_as_float((unsigned)(c      )); r.f[5] = __uint_as_float((unsigned)(c >> 32));
    r.f[6] = __uint_as_float((unsigned)(d      )); r.f[7] = __uint_as_float((unsigned)(d >> 32));
    return r;
}

__device__ __forceinline__ unsigned long long pack2(float lo, float hi) {
    return (unsigned long long)__float_as_uint(lo)
         | ((unsigned long long)__float_as_uint(hi) << 32);
}

__device__ __forceinline__ void stg_cs_32B(float* p, const float* v) {
    unsigned long long a = pack2(v[0], v[1]);
    unsigned long long b = pack2(v[2], v[3]);
    unsigned long long c = pack2(v[4], v[5]);
    unsigned long long d = pack2(v[6], v[7]);
    asm volatile("st.global.cs.v4.b64 [%0], {%1,%2,%3,%4};"
                 :: "l"(p), "l"(a), "l"(b), "l"(c), "l"(d) : "memory");
}

__global__ void __launch_bounds__(512, 4)
roi_align_kernel(const float* __restrict__ img,
                 const int*   __restrict__ rois,
                 float*       __restrict__ out)
{
    const int sub = threadIdx.x >> 7;        // 0..3: which bin in this CTA
    const int t   = threadIdx.x & 127;       // 0..127 within bin
    const size_t coff = (size_t)t * 8;       // 8 channels per thread

    // bin order: (((b*R + r)*POOL + py)*POOL + px)   -- b outermost
    int idx = blockIdx.x * BINS_PER_CTA + sub;
    const int px = idx % POOL; idx /= POOL;
    const int py = idx % POOL; idx /= POOL;
    const int r  = idx % R;    idx /= R;
    const int b  = idx;

    const int rx = rois[r * 4 + 0];
    const int ry = rois[r * 4 + 1];
    const int rw = rois[r * 4 + 2];
    const int rh = rois[r * 4 + 3];

    // coord = (p + 0.5) * (size/POOL) - 0.5   (matches reference fp32 order)
    const float sx = (float)rw / (float)POOL;
    const float sy = (float)rh / (float)POOL;

    const float cx = ((float)px + 0.5f) * sx - 0.5f;
    const float fx = floorf(cx);
    int x0 = (int)fx;            if (x0 < 0) x0 = 0;
    int x1 = (int)ceilf(cx);     if (x1 > rw - 1) x1 = rw - 1; if (x1 < 0) x1 = 0;
    const float wx = cx - fx;

    const float cy = ((float)py + 0.5f) * sy - 0.5f;
    const float fy = floorf(cy);
    int y0 = (int)fy;            if (y0 < 0) y0 = 0;
    int y1 = (int)ceilf(cy);     if (y1 > rh - 1) y1 = rh - 1; if (y1 < 0) y1 = 0;
    const float wy = cy - fy;

    const int gx0 = x0 + rx, gx1 = x1 + rx, gy0 = y0 + ry, gy1 = y1 + ry;

    const size_t base_b = (size_t)b * (W * W * C) + coff;

    const float* p00 = img + base_b + ((size_t)gy0 * W + gx0) * C;
    const float* p01 = img + base_b + ((size_t)gy0 * W + gx1) * C;
    const float* p10 = img + base_b + ((size_t)gy1 * W + gx0) * C;
    const float* p11 = img + base_b + ((size_t)gy1 * W + gx1) * C;

    F8 v00 = ldg_el_32B(p00);
    F8 v01 = ldg_el_32B(p01);
    F8 v10 = ldg_el_32B(p10);
    F8 v11 = ldg_el_32B(p11);

    float res[8];
#pragma unroll
    for (int i = 0; i < 8; i++) {
        float top = v00.f[i] + (v01.f[i] - v00.f[i]) * wx;
        float bot = v10.f[i] + (v11.f[i] - v10.f[i]) * wx;
        res[i] = top + (bot - top) * wy;
    }

    // output offset: r-major layout [r][b][py][px][c]
    const size_t obin = ((((size_t)r * B + b) * POOL + py) * POOL + px) * C;
    stg_cs_32B(out + obin + coff, res);
}

extern "C" void kernel_launch(void* const* d_in, const int* in_sizes, int n_in,
                              void* d_out, int out_size)
{
    const float* img  = (const float*)d_in[0];
    const int*   rois = (const int*)d_in[1];
    float*       out  = (float*)d_out;

    const int nblocks = (R * B * POOL * POOL) / BINS_PER_CTA;  // 3136
    roi_align_kernel<<<nblocks, 512>>>(img, rois, out);
}

// round 10
// speedup vs baseline: 1.0691x; 1.0691x over previous
#include <cuda_runtime.h>

// ROI-Align: img (8,64,64,1024) f32 NHWC, rois (32,4) int32 [x,y,w,h]
// out flat layout: [r][b][py][px][c]  (r-major), 32*8*7*7*1024 floats.
// 2 bins per 256-thread CTA (128 threads/bin, independent, no barriers):
// halves CTA dispatch ramp vs 1-bin CTAs while keeping fine-grained
// retirement (R7 showed 4-bin/512-thread CTAs hurt achieved DRAM BW).
// Bins ordered b-major for wave-level L2 locality.
// 8 channels/thread: 32-byte (v4.b64) evict_last loads, one 32-byte
// streaming (.cs v4.b64) output store.

#define POOL 7
#define B 8
#define R 32
#define C 1024
#define W 64
#define BINS_PER_CTA 2

struct F8 { float f[8]; };

__device__ __forceinline__ F8 ldg_el_32B(const void* p) {
    unsigned long long a, b, c, d;
    asm volatile("ld.global.nc.L2::evict_last.v4.b64 {%0,%1,%2,%3}, [%4];"
                 : "=l"(a), "=l"(b), "=l"(c), "=l"(d) : "l"(p));
    F8 r;
    r.f[0] = __uint_as_float((unsigned)(a      )); r.f[1] = __uint_as_float((unsigned)(a >> 32));
    r.f[2] = __uint_as_float((unsigned)(b      )); r.f[3] = __uint_as_float((unsigned)(b >> 32));
    r.f[4] = __uint_as_float((unsigned)(c      )); r.f[5] = __uint_as_float((unsigned)(c >> 32));
    r.f[6] = __uint_as_float((unsigned)(d      )); r.f[7] = __uint_as_float((unsigned)(d >> 32));
    return r;
}

__device__ __forceinline__ unsigned long long pack2(float lo, float hi) {
    return (unsigned long long)__float_as_uint(lo)
         | ((unsigned long long)__float_as_uint(hi) << 32);
}

__device__ __forceinline__ void stg_cs_32B(float* p, const float* v) {
    unsigned long long a = pack2(v[0], v[1]);
    unsigned long long b = pack2(v[2], v[3]);
    unsigned long long c = pack2(v[4], v[5]);
    unsigned long long d = pack2(v[6], v[7]);
    asm volatile("st.global.cs.v4.b64 [%0], {%1,%2,%3,%4};"
                 :: "l"(p), "l"(a), "l"(b), "l"(c), "l"(d) : "memory");
}

__global__ void __launch_bounds__(256, 8)
roi_align_kernel(const float* __restrict__ img,
                 const int*   __restrict__ rois,
                 float*       __restrict__ out)
{
    const int sub = threadIdx.x >> 7;        // 0..1: which bin in this CTA
    const int t   = threadIdx.x & 127;       // 0..127 within bin
    const size_t coff = (size_t)t * 8;       // 8 channels per thread

    // bin order: (((b*R + r)*POOL + py)*POOL + px)   -- b outermost
    int idx = blockIdx.x * BINS_PER_CTA + sub;
    const int px = idx % POOL; idx /= POOL;
    const int py = idx % POOL; idx /= POOL;
    const int r  = idx % R;    idx /= R;
    const int b  = idx;

    const int rx = rois[r * 4 + 0];
    const int ry = rois[r * 4 + 1];
    const int rw = rois[r * 4 + 2];
    const int rh = rois[r * 4 + 3];

    // coord = (p + 0.5) * (size/POOL) - 0.5   (matches reference fp32 order)
    const float sx = (float)rw / (float)POOL;
    const float sy = (float)rh / (float)POOL;

    const float cx = ((float)px + 0.5f) * sx - 0.5f;
    const float fx = floorf(cx);
    int x0 = (int)fx;            if (x0 < 0) x0 = 0;
    int x1 = (int)ceilf(cx);     if (x1 > rw - 1) x1 = rw - 1; if (x1 < 0) x1 = 0;
    const float wx = cx - fx;

    const float cy = ((float)py + 0.5f) * sy - 0.5f;
    const float fy = floorf(cy);
    int y0 = (int)fy;            if (y0 < 0) y0 = 0;
    int y1 = (int)ceilf(cy);     if (y1 > rh - 1) y1 = rh - 1; if (y1 < 0) y1 = 0;
    const float wy = cy - fy;

    const int gx0 = x0 + rx, gx1 = x1 + rx, gy0 = y0 + ry, gy1 = y1 + ry;

    const size_t base_b = (size_t)b * (W * W * C) + coff;

    const float* p00 = img + base_b + ((size_t)gy0 * W + gx0) * C;
    const float* p01 = img + base_b + ((size_t)gy0 * W + gx1) * C;
    const float* p10 = img + base_b + ((size_t)gy1 * W + gx0) * C;
    const float* p11 = img + base_b + ((size_t)gy1 * W + gx1) * C;

    F8 v00 = ldg_el_32B(p00);
    F8 v01 = ldg_el_32B(p01);
    F8 v10 = ldg_el_32B(p10);
    F8 v11 = ldg_el_32B(p11);

    float res[8];
#pragma unroll
    for (int i = 0; i < 8; i++) {
        float top = v00.f[i] + (v01.f[i] - v00.f[i]) * wx;
        float bot = v10.f[i] + (v11.f[i] - v10.f[i]) * wx;
        res[i] = top + (bot - top) * wy;
    }

    // output offset: r-major layout [r][b][py][px][c]
    const size_t obin = ((((size_t)r * B + b) * POOL + py) * POOL + px) * C;
    stg_cs_32B(out + obin + coff, res);
}

extern "C" void kernel_launch(void* const* d_in, const int* in_sizes, int n_in,
                              void* d_out, int out_size)
{
    const float* img  = (const float*)d_in[0];
    const int*   rois = (const int*)d_in[1];
    float*       out  = (float*)d_out;

    const int nblocks = (R * B * POOL * POOL) / BINS_PER_CTA;  // 6272
    roi_align_kernel<<<nblocks, 256>>>(img, rois, out);
}